// round 6
// baseline (speedup 1.0000x reference)
#include <cuda_runtime.h>
#include <cuda_bf16.h>
#include <stdint.h>

// Problem constants (match reference)
#define NSEG   8
#define KPTS   768
#define NPTS   10
#define NMAPS  7            // NSEG - SEG_DIST
#define WIMG   1024
#define KK     (KPTS * KPTS)          // 589824
#define STOT   (NMAPS * KK)           // 4128768  (each of 4 output rows)
#define PLANE  (WIMG * WIMG)          // 1048576

#define EP_BLOCKS  42                 // 2*NMAPS*KPTS / 256
#define TPB_MAP    1024               // (PLANE/4)/256 transpose blocks per map
#define WPB_MAP    2304               // KK/256 weight blocks per map

#define BURST      (EP_BLOCKS + TPB_MAP)        // 1066: ep + transpose(0)
#define GROUP      (WPB_MAP + TPB_MAP)          // 3328: weight(g) + transpose(g+1)
#define MIXED      (3 * TPB_MAP)                // 3072: 2:1 weight:transpose section
#define GRID_ALL   (BURST + 6 * GROUP + WPB_MAP)  // 23338

// PAF transposed to channel-interleaved (m, y, x, {c0,c1}): one 8B load fetches
// both channels of a sample point (halves scattered L1tex wavefronts).
__device__ float2 g_pafi[NMAPS * PLANE];     // 56 MB static scratch

// Endpoint samples (hoisted p=0 / p=9 gathers — depend on a single endpoint).
__device__ float2 g_e0[NMAPS * KPTS];
__device__ float2 g_e9[NMAPS * KPTS];

// Readiness counters (re-zeroed each launch by init_kernel).
__device__ int g_tctr[NMAPS];
__device__ int g_ectr;

// ---------------------------------------------------------------------------
__global__ void init_kernel() {
    if (threadIdx.x < NMAPS) g_tctr[threadIdx.x] = 0;
    if (threadIdx.x == NMAPS) g_ectr = 0;
}

// ---------------------------------------------------------------------------
__device__ __forceinline__ void do_transpose(const float* __restrict__ paf,
                                             int m, int tb) {
    int r4 = tb * 256 + threadIdx.x;
    const float4* c0p = (const float4*)(paf + (size_t)m * 2 * PLANE);
    const float4* c1p = (const float4*)(paf + (size_t)m * 2 * PLANE + PLANE);
    float4 c0 = __ldg(c0p + r4);
    float4 c1 = __ldg(c1p + r4);
    float4* dst = (float4*)&g_pafi[(size_t)m * PLANE + 4 * r4];
    dst[0] = make_float4(c0.x, c1.x, c0.y, c1.y);
    dst[1] = make_float4(c0.z, c1.z, c0.w, c1.w);
    __threadfence();
    __syncthreads();
    if (threadIdx.x == 0) atomicAdd(&g_tctr[m], 1);
}

__device__ __forceinline__ void do_weight(const int* __restrict__ sk,
                                          float* __restrict__ out,
                                          int m, int wb) {
    // Backstop wait: transpose(m) + endpoints were all issued at earlier
    // blockIdx positions, so this never deadlocks and rarely spins.
    // Poll with plain volatile loads (atomicAdd(ptr,0) polling would serialize
    // at the LTS atomic ALU under contention).
    if (threadIdx.x == 0) {
        volatile int* tc = (volatile int*)&g_tctr[m];
        volatile int* ec = (volatile int*)&g_ectr;
        while (*tc < TPB_MAP || *ec < EP_BLOCKS)
            __nanosleep(100);
    }
    __syncthreads();

    int local = wb * 256 + threadIdx.x;    // 0..KK-1 within map m
    int j = local % KPTS;                  // p1 index (lane-fast, coalesced)
    int i = local / KPTS;                  // p2 index (warp-uniform)

    int b1 = (m * KPTS + j) * 3;
    int b2 = ((m + 1) * KPTS + i) * 3;
    int x1 = __ldg(sk + b1 + 1);
    int y1 = __ldg(sk + b1 + 2);
    int x2 = __ldg(sk + b2 + 1);
    int y2 = __ldg(sk + b2 + 2);

    const float2* __restrict__ pafm = g_pafi + (size_t)m * PLANE;

    float2 e0 = __ldg(&g_e0[m * KPTS + j]);   // coalesced
    float2 e9 = __ldg(&g_e9[m * KPTS + i]);   // broadcast
    float s0 = e0.x + e9.x;
    float s1 = e0.y + e9.y;

#pragma unroll
    for (int p = 1; p < NPTS - 1; p++) {
        // integer floor-div by 9; operands nonnegative so C '/' == floor
        int lx = (x1 * (NPTS - 1 - p) + x2 * p) / (NPTS - 1);
        int ly = (y1 * (NPTS - 1 - p) + y2 * p) / (NPTS - 1);
        float2 v = __ldg(&pafm[ly * WIMG + lx]);
        s0 += v.x;
        s1 += v.y;
    }

    float dx = (float)(x2 - x1);
    float dy = (float)(y2 - y1);
    float R2 = dx * dx + dy * dy;
    float R  = sqrtf(R2);
    // li = mean_p sum_c (tv_c/R)*paf_c = (dx*s0 + dy*s1)/(R*NPTS); NaN (R==0) -> 0
    float li = (R2 > 0.f) ? (dx * s0 + dy * s1) / (R * (float)NPTS) : 0.f;

    int idx = m * KK + local;
    // Streaming stores: don't evict the L2-resident PAF with the 66MB output.
    __stcs(&out[idx],            (float)(m * KPTS + j));       // edges_indices[0]
    __stcs(&out[STOT + idx],     (float)((m + 1) * KPTS + i)); // edges_indices[1]
    __stcs(&out[2 * STOT + idx], li);                          // edges_costs[0]
    __stcs(&out[3 * STOT + idx], R);                           // edges_costs[1]
}

// ---------------------------------------------------------------------------
// Mega kernel with role-INTERLEAVED blockIdx layout (blocks launch in order,
// so producers must be woven between consumers to actually overlap):
//   [0,42)            endpoint blocks
//   [42,1066)         transpose map 0
//   groups g=0..5 (3328 blocks each):
//       first 3072:   pattern {weight(g), weight(g), transpose(g+1)}
//       last  256:    weight(g)
//   tail 2304:        weight map 6
__global__ void __launch_bounds__(256) mega_kernel(
    const int* __restrict__ sk, const float* __restrict__ paf,
    float* __restrict__ out)
{
    unsigned bid = blockIdx.x;

    if (bid < BURST) {
        if (bid < EP_BLOCKS) {
            int t = bid * 256 + threadIdx.x;             // over 2*NMAPS*KPTS
            int which = t / (NMAPS * KPTS);              // 0 -> E0, 1 -> E9
            int r = t - which * (NMAPS * KPTS);
            int m = r / KPTS;
            int q = r - m * KPTS;
            int base = ((m + which) * KPTS + q) * 3;     // E0: seg m; E9: seg m+1
            int x = __ldg(sk + base + 1);
            int y = __ldg(sk + base + 2);
            const float* pm = paf + (size_t)m * 2 * PLANE;
            float c0 = __ldg(pm + y * WIMG + x);
            float c1 = __ldg(pm + PLANE + y * WIMG + x);
            (which ? g_e9 : g_e0)[r] = make_float2(c0, c1);
            __threadfence();
            __syncthreads();
            if (threadIdx.x == 0) atomicAdd(&g_ectr, 1);
        } else {
            do_transpose(paf, 0, bid - EP_BLOCKS);
        }
        return;
    }

    unsigned rem = bid - BURST;
    int g = rem / GROUP;
    if (g < 6) {
        int k = rem - g * GROUP;
        if (k < MIXED) {
            int q = k / 3, r = k % 3;
            if (r == 2) do_transpose(paf, g + 1, q);       // transpose map g+1
            else        do_weight(sk, out, g, 2 * q + r);  // weight map g
        } else {
            do_weight(sk, out, g, 2 * TPB_MAP + (k - MIXED));
        }
    } else {
        do_weight(sk, out, 6, rem - 6 * GROUP);            // tail: weight map 6
    }
}

extern "C" void kernel_launch(void* const* d_in, const int* in_sizes, int n_in,
                              void* d_out, int out_size) {
    const int*   sk  = (const int*)d_in[0];     // skeletons (6144, 3) int32
    const float* paf = (const float*)d_in[1];   // PAF (7, 2, 1024, 1024) float32
    float* out = (float*)d_out;

    init_kernel<<<1, 32>>>();
    mega_kernel<<<GRID_ALL, 256>>>(sk, paf, out);
}

// round 7
// speedup vs baseline: 1.0394x; 1.0394x over previous
#include <cuda_runtime.h>
#include <cuda_bf16.h>
#include <stdint.h>

// Problem constants (match reference)
#define NSEG   8
#define KPTS   768
#define NPTS   10
#define NMAPS  7            // NSEG - SEG_DIST
#define WIMG   1024
#define KK     (KPTS * KPTS)          // 589824
#define STOT   (NMAPS * KK)           // 4128768  (each of 4 output rows)
#define PLANE  (WIMG * WIMG)          // 1048576

#define TPB_MAP   ((PLANE / 8) / 256)                // 512 transpose blocks per map (8 px/thread)
#define T_ALL     (NMAPS * TPB_MAP)                  // 3584
#define EP_BLOCKS ((2 * NMAPS * KPTS + 255) / 256)   // 42
#define W_ALL     (STOT / 256)                       // 16128

// PAF transposed to channel-interleaved (m, y, x, {c0,c1}): one 8B load fetches
// both channels of a sample point (halves scattered L1tex wavefronts).
__device__ float2 g_pafi[NMAPS * PLANE];     // 56 MB static scratch

// Endpoint samples (hoisted p=0 / p=9 gathers — depend on a single endpoint).
__device__ float2 g_e0[NMAPS * KPTS];
__device__ float2 g_e9[NMAPS * KPTS];

// Packed coordinates: g_pack[seg*KPTS+q] = x | (y<<16). One load instead of two
// stride-3 loads, and one IMAD interpolates both axes (x-part < 2^16, no carry).
__device__ unsigned g_pack[NSEG * KPTS];

// ---------------------------------------------------------------------------
// Prologue: [0,T_ALL) transpose blocks (8 px/thread, 4 loads in flight),
//           [T_ALL, T_ALL+EP_BLOCKS) endpoint + coordinate-packing blocks.
__global__ void __launch_bounds__(256) prologue_kernel(const int* __restrict__ sk,
                                                       const float* __restrict__ paf) {
    unsigned bid = blockIdx.x;

    if (bid < T_ALL) {
        int m  = bid / TPB_MAP;
        int r8 = ((bid - m * TPB_MAP) * 256 + threadIdx.x) * 2;  // float4 pair index
        const float4* c0p = (const float4*)(paf + (size_t)m * 2 * PLANE);
        const float4* c1p = (const float4*)(paf + (size_t)m * 2 * PLANE + PLANE);
        // 4 independent loads in flight (MLP=4) — transpose was latency-bound at MLP=2.
        float4 c0a = __ldg(c0p + r8);
        float4 c0b = __ldg(c0p + r8 + 1);
        float4 c1a = __ldg(c1p + r8);
        float4 c1b = __ldg(c1p + r8 + 1);
        float4* dst = (float4*)&g_pafi[(size_t)m * PLANE + 4 * r8];
        dst[0] = make_float4(c0a.x, c1a.x, c0a.y, c1a.y);
        dst[1] = make_float4(c0a.z, c1a.z, c0a.w, c1a.w);
        dst[2] = make_float4(c0b.x, c1b.x, c0b.y, c1b.y);
        dst[3] = make_float4(c0b.z, c1b.z, c0b.w, c1b.w);
        return;
    }

    int t = (bid - T_ALL) * 256 + threadIdx.x;       // over 2*NMAPS*KPTS
    if (t >= 2 * NMAPS * KPTS) return;
    int which = t / (NMAPS * KPTS);                  // 0 -> E0, 1 -> E9
    int r = t - which * (NMAPS * KPTS);
    int m = r / KPTS;
    int q = r - m * KPTS;
    int seg = m + which;                             // E0: seg m; E9: seg m+1
    int base = (seg * KPTS + q) * 3;
    int x = __ldg(sk + base + 1);
    int y = __ldg(sk + base + 2);
    // Pack coords: segs 0..6 via E0 threads, 1..7 via E9 (overlap writes same value).
    g_pack[seg * KPTS + q] = (unsigned)x | ((unsigned)y << 16);
    const float* pm = paf + (size_t)m * 2 * PLANE;
    float c0 = __ldg(pm + y * WIMG + x);
    float c1 = __ldg(pm + PLANE + y * WIMG + x);
    (which ? g_e9 : g_e0)[r] = make_float2(c0, c1);
}

// ---------------------------------------------------------------------------
__global__ void __launch_bounds__(256) weight_kernel(
    float* __restrict__ out)         // [i1 | i2 | li | R], each STOT floats
{
    int idx = blockIdx.x * 256 + threadIdx.x;        // 0..STOT-1
    int j = idx % KPTS;              // p1 index (lane-fast, coalesced)
    int t = idx / KPTS;
    int i = t % KPTS;                // p2 index (warp-uniform)
    int m = t / KPTS;                // map (block-uniform)

    unsigned P1 = __ldg(&g_pack[m * KPTS + j]);        // coalesced, 1 line/warp
    unsigned P2 = __ldg(&g_pack[(m + 1) * KPTS + i]);  // uniform broadcast

    const float2* __restrict__ pafm = g_pafi + (size_t)m * PLANE;

    float2 e0 = __ldg(&g_e0[m * KPTS + j]);   // coalesced
    float2 e9 = __ldg(&g_e9[m * KPTS + i]);   // broadcast
    float s0 = e0.x + e9.x;
    float s1 = e0.y + e9.y;

#pragma unroll
    for (int p = 1; p < NPTS - 1; p++) {
        // Both axes in one IMAD: x-part = x1*(9-p)+x2*p <= 9207 < 2^16 (no carry).
        unsigned S  = P1 * (unsigned)(NPTS - 1 - p) + P2 * (unsigned)p;
        unsigned lx = (S & 0xFFFFu) / 9u;     // floor-div (nonnegative)
        unsigned ly = (S >> 16) / 9u;
        float2 v = __ldg(&pafm[ly * WIMG + lx]);
        s0 += v.x;
        s1 += v.y;
    }

    float dx = (float)(int)((P2 & 0xFFFFu) - (P1 & 0xFFFFu));
    float dy = (float)(int)((P2 >> 16) - (P1 >> 16));
    float R2 = dx * dx + dy * dy;
    float R  = sqrtf(R2);
    // li = mean_p sum_c (tv_c/R)*paf_c = (dx*s0 + dy*s1)/(R*NPTS); NaN (R==0) -> 0
    float li = (R2 > 0.f) ? (dx * s0 + dy * s1) / (R * (float)NPTS) : 0.f;

    // Streaming stores: don't evict the L2-resident PAF with the 66MB output.
    __stcs(&out[idx],            (float)(m * KPTS + j));       // edges_indices[0]
    __stcs(&out[STOT + idx],     (float)((m + 1) * KPTS + i)); // edges_indices[1]
    __stcs(&out[2 * STOT + idx], li);                          // edges_costs[0]
    __stcs(&out[3 * STOT + idx], R);                           // edges_costs[1]
}

extern "C" void kernel_launch(void* const* d_in, const int* in_sizes, int n_in,
                              void* d_out, int out_size) {
    const int*   sk  = (const int*)d_in[0];     // skeletons (6144, 3) int32
    const float* paf = (const float*)d_in[1];   // PAF (7, 2, 1024, 1024) float32
    float* out = (float*)d_out;

    prologue_kernel<<<T_ALL + EP_BLOCKS, 256>>>(sk, paf);
    weight_kernel<<<W_ALL, 256>>>(out);
}